// round 12
// baseline (speedup 1.0000x reference)
#include <cuda_runtime.h>
#include <cstdint>

typedef unsigned long long u64;

#define Bn 1024
#define Tn 512
#define Ln 64
#define Nn 8
#define Hn 128
#define HP 130              /* padded float2 row for h buffers (bank-spread) */
#define DIn 32
#define DOn 16
#define RROWS 8
#define PAIRS 4
#define NCTA (Bn / RROWS)   /* 128 */
#define STHR 512
#define XFULL ((size_t)Bn * Tn * DOn)

// z-path scratch: [t][cta][pair][l] as packed float2 (u64). 128 MB.
__device__ u64 zbuf[(size_t)Tn * NCTA * PAIRS * Ln];

// ---------------- scan-kernel shared memory (~224 KB) ------------------------
struct __align__(16) Smem {
    float fW1t[Hn][68];    // f_W1 z-part transposed [j][k]; 68 == 4 (mod 32)
    float fW2t[Hn][132];   // f_W2 transposed; 132 == 4 (mod 32)
    float gW1t[Hn][68];
    float gW2t[Hn][132];
    float2 z2[PAIRS][Ln];  // state, row-pairs packed: .x = row 2p, .y = row 2p+1
    float2 h1f[PAIRS][HP];
    float2 h2f[PAIRS][HP];
    float2 h1g[PAIRS][HP];
    float2 h2g[PAIRS][HP];
    float2 dws[PAIRS][Nn];
};

// ---------------- f32x2 packed helpers ---------------------------------------
__device__ __forceinline__ u64 dup2f(float v) {
    u64 r; asm("mov.b64 %0,{%1,%1};" : "=l"(r) : "f"(v)); return r;
}
__device__ __forceinline__ u64 pk2(float lo, float hi) {
    u64 r; asm("mov.b64 %0,{%1,%2};" : "=l"(r) : "f"(lo), "f"(hi)); return r;
}
__device__ __forceinline__ void unpk2(u64 v, float& lo, float& hi) {
    asm("mov.b64 {%0,%1},%2;" : "=f"(lo), "=f"(hi) : "l"(v));
}
__device__ __forceinline__ u64 f2fma(u64 a, u64 b, u64 c) {
    u64 d; asm("fma.rn.f32x2 %0,%1,%2,%3;" : "=l"(d) : "l"(a), "l"(b), "l"(c)); return d;
}
__device__ __forceinline__ u64 f2add(u64 a, u64 b) {
    u64 d; asm("add.rn.f32x2 %0,%1,%2;" : "=l"(d) : "l"(a), "l"(b)); return d;
}

// softplus(x) = max(x,0) + log1p(exp(-|x|))
__device__ __forceinline__ float softplus1(float x) {
    float e = __expf(-fabsf(x));
    return fmaxf(x, 0.f) + 0.69314718055994531f * __log2f(1.f + e);
}
// tanh(x) = 1 - 2/(exp(2x)+1)
__device__ __forceinline__ float tanh1(float x) {
    float e = __expf(2.f * x);
    return 1.f - __fdividef(2.f, e + 1.f);
}
__device__ __forceinline__ u64 tanh2(u64 v) {
    float lo, hi; unpk2(v, lo, hi);
    return pk2(tanh1(lo), tanh1(hi));
}

// ---------------- main persistent scan kernel --------------------------------
__global__ void __launch_bounds__(STHR, 1)
sde_scan_kernel(const float* __restrict__ init_noise, const float* __restrict__ dw_noise,
                const float* __restrict__ ts,   const float* __restrict__ embW,
                const float* __restrict__ embb, const float* __restrict__ fW1,
                const float* __restrict__ fb1,  const float* __restrict__ fW2,
                const float* __restrict__ fb2,  const float* __restrict__ fW3,
                const float* __restrict__ fb3,  const float* __restrict__ gW1,
                const float* __restrict__ gb1,  const float* __restrict__ gW2,
                const float* __restrict__ gb2,  const float* __restrict__ gW3,
                const float* __restrict__ gb3)
{
    extern __shared__ __align__(16) char smraw[];
    Smem& sm = *reinterpret_cast<Smem*>(smraw);
    const int tid = threadIdx.x;
    const int w = tid >> 5, lane = tid & 31;
    // ph1/ph2 mapping: warp-uniform path; thread = (j, path, pair-group)
    const int path = w & 1;                 // 0=f, 1=g (uniform per warp)
    const int pg = w >> 3;                  // pair-group: pairs {2pg, 2pg+1}
    const int j = ((w >> 1) & 3) * 32 + lane;   // neuron 0..127
    const int pA = 2 * pg, pB = 2 * pg + 1;
    const int rowbase = blockIdx.x * RROWS;

    // ---- stage SMEM-resident weights (quarter-split over 512 threads) ----
    {
        const int jj = tid & 127, q = tid >> 7;
        if (q == 0) {
#pragma unroll 4
            for (int k = 0; k < Ln; k++) sm.fW1t[jj][k] = fW1[(k + 1) * Hn + jj];
        } else if (q == 1) {
#pragma unroll 4
            for (int k = 0; k < Ln; k++) sm.gW1t[jj][k] = gW1[(k + 1) * Hn + jj];
        } else if (q == 2) {
#pragma unroll 4
            for (int k = 0; k < Hn; k++) sm.fW2t[jj][k] = fW2[k * Hn + jj];
        } else {
#pragma unroll 4
            for (int k = 0; k < Hn; k++) sm.gW2t[jj][k] = gW2[k * Hn + jj];
        }
    }

    // ---- per-thread register params (path-selected) ----
    const float w10 = path ? __ldg(gW1 + j) : __ldg(fW1 + j);
    const float b1  = path ? __ldg(gb1 + j) : __ldg(fb1 + j);
    const float b2  = path ? __ldg(gb2 + j) : __ldg(fb2 + j);
    // ph3 mappings
    const int kh3 = tid & 1, pf = (tid >> 1) & 3, lf = tid >> 3;  // f3
    const float bf3v = __ldg(fb3 + lf);
    const float bg3o = __ldg(gb3 + tid);                          // g3: o = tid
    const int ng = tid & 7;                                       // einsum n-lane

    // warp-uniform SMEM array selectors
    const float (*W1p)[68]  = path ? sm.gW1t : sm.fW1t;
    const float (*W2p)[132] = path ? sm.gW2t : sm.fW2t;
    float2 (*h1p)[HP] = path ? sm.h1g : sm.h1f;
    float2 (*h2p)[HP] = path ? sm.h2g : sm.h2f;

    // ---- z0 = init_noise @ emb_W + emb_b; store to zbuf[t=0] ----
    if (tid < 256) {
        int l = tid & 63, p = tid >> 6;
        float ax = __ldg(embb + l), ay = ax;
#pragma unroll 4
        for (int i = 0; i < DIn; i++) {
            float we = embW[i * Ln + l];
            ax = fmaf(init_noise[(rowbase + 2 * p) * DIn + i], we, ax);
            ay = fmaf(init_noise[(rowbase + 2 * p + 1) * DIn + i], we, ay);
        }
        sm.z2[p][l] = make_float2(ax, ay);
        zbuf[(size_t)blockIdx.x * (PAIRS * Ln) + tid] = *(const u64*)&sm.z2[p][l];
    }
    __syncthreads();

    // ---- 511 Euler-Maruyama steps, 3 barriers each --------------------------
    for (int s = 0; s < Tn - 1; s++) {
        const float tcur = __ldg(ts + s);
        const float dt = __ldg(ts + s + 1) - tcur;
        const float sq = sqrtf(dt);
        if (tid < 32) {   // Brownian increments (consumed in ph3, 2 bars later)
            int p = tid >> 3, n = tid & 7;
            const float* dwp = dw_noise + ((size_t)s * Bn + rowbase + 2 * p) * Nn + n;
            sm.dws[p][n] = make_float2(dwp[0] * sq, dwp[Nn] * sq);
        }

        // ===== ph1: layer1 of own path, pairs {pA,pB} =====
        {
            u64 z0 = dup2f(0.f);
            u64 ini = dup2f(fmaf(w10, tcur, b1));
            u64 aA[2] = { ini, ini }, aB[2] = { z0, z0 };
#pragma unroll 4
            for (int c = 0; c < Ln / 4; c++) {
                float4 wv = *(const float4*)&W1p[j][4 * c];
                u64 w0 = dup2f(wv.x), w1 = dup2f(wv.y), w2 = dup2f(wv.z), w3 = dup2f(wv.w);
                ulonglong2 xa0 = *(const ulonglong2*)&sm.z2[pA][4 * c];
                ulonglong2 xa1 = *(const ulonglong2*)&sm.z2[pA][4 * c + 2];
                ulonglong2 xb0 = *(const ulonglong2*)&sm.z2[pB][4 * c];
                ulonglong2 xb1 = *(const ulonglong2*)&sm.z2[pB][4 * c + 2];
                aA[0] = f2fma(w0, xa0.x, aA[0]);
                aB[0] = f2fma(w1, xa0.y, aB[0]);
                aA[0] = f2fma(w2, xa1.x, aA[0]);
                aB[0] = f2fma(w3, xa1.y, aB[0]);
                aA[1] = f2fma(w0, xb0.x, aA[1]);
                aB[1] = f2fma(w1, xb0.y, aB[1]);
                aA[1] = f2fma(w2, xb1.x, aA[1]);
                aB[1] = f2fma(w3, xb1.y, aB[1]);
            }
#pragma unroll
            for (int e = 0; e < 2; e++) {
                u64 t = f2add(aA[e], aB[e]);
                float lo, hi; unpk2(t, lo, hi);
                h1p[2 * pg + e][j] = make_float2(softplus1(lo), softplus1(hi));
            }
        }
        __syncthreads();

        // ===== ph2: layer2 of own path =====
        {
            u64 z0 = dup2f(0.f);
            u64 ini = dup2f(b2);
            u64 aA[2] = { ini, ini }, aB[2] = { z0, z0 };
#pragma unroll 4
            for (int c = 0; c < Hn / 4; c++) {
                float4 wv = *(const float4*)&W2p[j][4 * c];
                u64 w0 = dup2f(wv.x), w1 = dup2f(wv.y), w2 = dup2f(wv.z), w3 = dup2f(wv.w);
                ulonglong2 xa0 = *(const ulonglong2*)&h1p[pA][4 * c];
                ulonglong2 xa1 = *(const ulonglong2*)&h1p[pA][4 * c + 2];
                ulonglong2 xb0 = *(const ulonglong2*)&h1p[pB][4 * c];
                ulonglong2 xb1 = *(const ulonglong2*)&h1p[pB][4 * c + 2];
                aA[0] = f2fma(w0, xa0.x, aA[0]);
                aB[0] = f2fma(w1, xa0.y, aB[0]);
                aA[0] = f2fma(w2, xa1.x, aA[0]);
                aB[0] = f2fma(w3, xa1.y, aB[0]);
                aA[1] = f2fma(w0, xb0.x, aA[1]);
                aB[1] = f2fma(w1, xb0.y, aB[1]);
                aA[1] = f2fma(w2, xb1.x, aA[1]);
                aB[1] = f2fma(w3, xb1.y, aB[1]);
            }
#pragma unroll
            for (int e = 0; e < 2; e++) {
                u64 t = f2add(aA[e], aB[e]);
                float lo, hi; unpk2(t, lo, hi);
                h2p[2 * pg + e][j] = make_float2(softplus1(lo), softplus1(hi));
            }
        }
        __syncthreads();

        // ===== ph3: f3 (interleaved k-split) + g3 (o=tid) + einsum + z-update =====
        {
            const u64 one2 = dup2f(1.f);
            // f3 accumulators: pair pf, output lf, k ≡ kh3 (mod 2)
            u64 fa0 = kh3 ? dup2f(0.f) : dup2f(bf3v);
            u64 fa1 = dup2f(0.f);
            // g3 accumulators: output o = tid, all 4 pairs
            u64 acc0 = dup2f(bg3o), acc1 = acc0, acc2 = acc0, acc3 = acc0;
            const float* fp = fW3 + lf;
            const float* gp = gW3 + tid;
#pragma unroll 4
            for (int c = 0; c < Hn / 4; c++) {
                // f3: k = 4c + kh3, 4c + 2 + kh3 (this lane's parity)
                u64 fw0 = dup2f(__ldg(fp + (4 * c + kh3) * Ln));
                u64 fw1 = dup2f(__ldg(fp + (4 * c + 2 + kh3) * Ln));
                fa0 = f2fma(fw0, *(const u64*)&sm.h2f[pf][4 * c + kh3], fa0);
                fa1 = f2fma(fw1, *(const u64*)&sm.h2f[pf][4 * c + 2 + kh3], fa1);
                // g3: k-rows 4c .. 4c+3 (coalesced LDG.32 over warp)
                u64 g0 = dup2f(__ldg(gp + (size_t)(4 * c) * (Ln * Nn)));
                u64 g1 = dup2f(__ldg(gp + (size_t)(4 * c + 1) * (Ln * Nn)));
                u64 g2 = dup2f(__ldg(gp + (size_t)(4 * c + 2) * (Ln * Nn)));
                u64 g3v = dup2f(__ldg(gp + (size_t)(4 * c + 3) * (Ln * Nn)));
                ulonglong2 h0 = *(const ulonglong2*)&sm.h2g[0][4 * c];
                ulonglong2 h0b = *(const ulonglong2*)&sm.h2g[0][4 * c + 2];
                acc0 = f2fma(g0, h0.x, acc0);
                acc0 = f2fma(g1, h0.y, acc0);
                acc0 = f2fma(g2, h0b.x, acc0);
                acc0 = f2fma(g3v, h0b.y, acc0);
                ulonglong2 h1 = *(const ulonglong2*)&sm.h2g[1][4 * c];
                ulonglong2 h1b = *(const ulonglong2*)&sm.h2g[1][4 * c + 2];
                acc1 = f2fma(g0, h1.x, acc1);
                acc1 = f2fma(g1, h1.y, acc1);
                acc1 = f2fma(g2, h1b.x, acc1);
                acc1 = f2fma(g3v, h1b.y, acc1);
                ulonglong2 h2 = *(const ulonglong2*)&sm.h2g[2][4 * c];
                ulonglong2 h2b = *(const ulonglong2*)&sm.h2g[2][4 * c + 2];
                acc2 = f2fma(g0, h2.x, acc2);
                acc2 = f2fma(g1, h2.y, acc2);
                acc2 = f2fma(g2, h2b.x, acc2);
                acc2 = f2fma(g3v, h2b.y, acc2);
                ulonglong2 h3 = *(const ulonglong2*)&sm.h2g[3][4 * c];
                ulonglong2 h3b = *(const ulonglong2*)&sm.h2g[3][4 * c + 2];
                acc3 = f2fma(g0, h3.x, acc3);
                acc3 = f2fma(g1, h3.y, acc3);
                acc3 = f2fma(g2, h3b.x, acc3);
                acc3 = f2fma(g3v, h3b.y, acc3);
            }
            // einsum partials: pa[p] = tanh(acc[p]) * dws[p][ng], reduce over ng
            u64 pa0, pa1, pa2, pa3;
            {
                u64 zz = dup2f(0.f);
                pa0 = f2fma(tanh2(acc0), *(const u64*)&sm.dws[0][ng], zz);
                pa1 = f2fma(tanh2(acc1), *(const u64*)&sm.dws[1][ng], zz);
                pa2 = f2fma(tanh2(acc2), *(const u64*)&sm.dws[2][ng], zz);
                pa3 = f2fma(tanh2(acc3), *(const u64*)&sm.dws[3][ng], zz);
#pragma unroll
                for (int m = 1; m <= 4; m <<= 1) {
                    pa0 = f2fma(one2, __shfl_xor_sync(0xffffffffu, pa0, m), pa0);
                    pa1 = f2fma(one2, __shfl_xor_sync(0xffffffffu, pa1, m), pa1);
                    pa2 = f2fma(one2, __shfl_xor_sync(0xffffffffu, pa2, m), pa2);
                    pa3 = f2fma(one2, __shfl_xor_sync(0xffffffffu, pa3, m), pa3);
                }
            }
            // f3 combine across kh lanes; kh3==0 lane updates z for (pf, lf)
            u64 fs = f2add(fa0, fa1);
            fs = f2add(fs, __shfl_xor_sync(0xffffffffu, fs, 1));
            if (kh3 == 0) {
                u64 fv = tanh2(fs);
                u64 geo = (pf == 0) ? pa0 : (pf == 1) ? pa1 : (pf == 2) ? pa2 : pa3;
                u64 z = *(const u64*)&sm.z2[pf][lf];
                z = f2fma(fv, dup2f(dt), z);
                z = f2fma(one2, geo, z);
                *(u64*)&sm.z2[pf][lf] = z;
                zbuf[((size_t)(s + 1) * NCTA + blockIdx.x) * (PAIRS * Ln)
                     + pf * Ln + lf] = z;
            }
        }
        __syncthreads();
    }
}

// ---------------- readout kernel: x = relu(z@rW1+b1)@rW2+b2 ------------------
#define RO_TS 32   /* time steps per block */
struct __align__(16) RoSmem {
    float rw1t[Hn][68];     // rW1 transposed [j][l]
    float w2t[DOn][130];    // rW2 transposed [d][k], pad 130
    float2 zt[PAIRS][Ln];   // current z tile (2 KB)
    float h1T[RROWS][132];  // stage-1 output, scalar per row, pad 132
};

__global__ void __launch_bounds__(256, 4)
readout_kernel(const float* __restrict__ rW1, const float* __restrict__ rb1,
               const float* __restrict__ rW2, const float* __restrict__ rb2,
               float* __restrict__ out)
{
    extern __shared__ __align__(16) char smraw[];
    RoSmem& sm = *reinterpret_cast<RoSmem*>(smraw);
    const int tid = threadIdx.x;
    const int cta = blockIdx.x & (NCTA - 1);
    const int slice = blockIdx.x >> 7;
    const int rowbase = cta * RROWS;

    // stage rW1 transposed: [j][l], coalesced LDG over j
    {
        const int jj = tid & 127, half = tid >> 7;
#pragma unroll 4
        for (int l = half * 32; l < half * 32 + 32; l++)
            sm.rw1t[jj][l] = rW1[l * Hn + jj];
    }
    // stage rW2 transposed: [d][k]
    for (int i = tid; i < Hn * DOn; i += 256) {
        int d = i & 15, k = i >> 4;
        sm.w2t[d][k] = rW2[i];
    }
    const float rb1v = __ldg(rb1 + (tid & 127));
    const int jr = tid & 127, p0 = (tid >> 7) * 2;             // stage-1 mapping
    const int row2 = tid >> 5, kh5 = (tid >> 4) & 1, d5 = tid & 15;  // stage-2
    const float rb2v = __ldg(rb2 + d5);
    __syncthreads();

    for (int it = 0; it < RO_TS; it++) {
        const int t = slice * RO_TS + it;
        // load z tile
        ((u64*)&sm.zt[0][0])[tid] =
            zbuf[((size_t)t * NCTA + cta) * (PAIRS * Ln) + tid];
        __syncthreads();
        // stage 1: h = relu(z @ rW1 + b1); thread = (jr, 2 pairs); write h1T
        {
            u64 aA[2], aB[2];
            u64 bi = dup2f(rb1v), z0 = dup2f(0.f);
            aA[0] = bi; aA[1] = bi; aB[0] = z0; aB[1] = z0;
#pragma unroll 4
            for (int c = 0; c < Ln / 4; c++) {
                float4 w = *(const float4*)&sm.rw1t[jr][4 * c];
                u64 w0 = dup2f(w.x), w1 = dup2f(w.y), w2 = dup2f(w.z), w3 = dup2f(w.w);
#pragma unroll
                for (int e = 0; e < 2; e++) {
                    ulonglong2 x0 = *(const ulonglong2*)&sm.zt[p0 + e][4 * c];
                    ulonglong2 x1 = *(const ulonglong2*)&sm.zt[p0 + e][4 * c + 2];
                    aA[e] = f2fma(w0, x0.x, aA[e]);
                    aB[e] = f2fma(w1, x0.y, aB[e]);
                    aA[e] = f2fma(w2, x1.x, aA[e]);
                    aB[e] = f2fma(w3, x1.y, aB[e]);
                }
            }
#pragma unroll
            for (int e = 0; e < 2; e++) {
                u64 tv = f2add(aA[e], aB[e]);
                float lo, hi; unpk2(tv, lo, hi);
                sm.h1T[2 * (p0 + e)][jr]     = fmaxf(lo, 0.f);
                sm.h1T[2 * (p0 + e) + 1][jr] = fmaxf(hi, 0.f);
            }
        }
        __syncthreads();
        // stage 2: x = h @ rW2 + b2; thread = (row2, kh5, d5), f32x2 over k-pairs
        {
            u64 acc = dup2f(0.f);
            const float* hT = &sm.h1T[row2][kh5 * 64];
            const float* wT = &sm.w2t[d5][kh5 * 64];
#pragma unroll 8
            for (int kk = 0; kk < 64; kk += 2)
                acc = f2fma(*(const u64*)&hT[kk], *(const u64*)&wT[kk], acc);
            float lo, hi; unpk2(acc, lo, hi);
            float a = lo + hi;
            a += __shfl_xor_sync(0xffffffffu, a, 16);
            if (kh5 == 0) {
                a += rb2v;
                size_t row = (size_t)rowbase + row2;
                out[(row * Tn + t) * DOn + d5] = a;
                if ((t & 7) == 0)
                    out[XFULL + (row * (Tn / 8) + (t >> 3)) * DOn + d5] = a;
            }
        }
        __syncthreads();
    }
}

extern "C" void kernel_launch(void* const* d_in, const int* in_sizes, int n_in,
                              void* d_out, int out_size) {
    (void)in_sizes; (void)n_in; (void)out_size;
    cudaFuncSetAttribute(sde_scan_kernel, cudaFuncAttributeMaxDynamicSharedMemorySize,
                         (int)sizeof(Smem));
    cudaFuncSetAttribute(readout_kernel, cudaFuncAttributeMaxDynamicSharedMemorySize,
                         (int)sizeof(RoSmem));
    sde_scan_kernel<<<NCTA, STHR, sizeof(Smem)>>>(
        (const float*)d_in[0],  (const float*)d_in[1],  (const float*)d_in[2],
        (const float*)d_in[3],  (const float*)d_in[4],  (const float*)d_in[5],
        (const float*)d_in[6],  (const float*)d_in[7],  (const float*)d_in[8],
        (const float*)d_in[9],  (const float*)d_in[10], (const float*)d_in[11],
        (const float*)d_in[12], (const float*)d_in[13], (const float*)d_in[14],
        (const float*)d_in[15], (const float*)d_in[16]);
    readout_kernel<<<NCTA * (Tn / RO_TS), 256, sizeof(RoSmem)>>>(
        (const float*)d_in[17], (const float*)d_in[18],
        (const float*)d_in[19], (const float*)d_in[20],
        (float*)d_out);
}

// round 13
// speedup vs baseline: 1.1366x; 1.1366x over previous
#include <cuda_runtime.h>
#include <cstdint>

typedef unsigned long long u64;

#define Bn 1024
#define Tn 512
#define Ln 64
#define Nn 8
#define Hn 128
#define DIn 32
#define DOn 16
#define RROWS 8
#define PAIRS 4
#define NCTA (Bn / RROWS)   /* 128 */
#define NTHR 256
#define XFULL ((size_t)Bn * Tn * DOn)

// z-path scratch: [t][cta][pair][l] as packed float2 (u64). 128 MB.
__device__ u64 zbuf[(size_t)Tn * NCTA * PAIRS * Ln];

// ---------------- scan-kernel shared memory (230,016 B) ----------------------
struct __align__(16) Smem {
    float fW1t[Hn][68];     // f_W1 z-part transposed [j][k]; k-packed consumption
    float fW2t[Hn][132];    // f_W2 transposed
    float gW1t[Hn][68];
    float gW2t[Hn][132];
    float2 z2[PAIRS][Ln];   // canonical state, row-pairs packed
    float  zs[RROWS][68];   // scalar state per row (ph1 k-packed input)
    float  h1fs[RROWS][132];// f hidden-1 scalar per row
    float  h1gs[RROWS][132];
    float2 h2f[PAIRS][Hn];  // pair-packed for ph3
    float2 h2g[PAIRS][Hn];
    float2 fo[PAIRS][Ln];   // drift output
    float2 geo[PAIRS][Ln];  // diffusion einsum output
    float2 dws[PAIRS][Nn];
};

// ---------------- f32x2 packed helpers ---------------------------------------
__device__ __forceinline__ u64 dup2f(float v) {
    u64 r; asm("mov.b64 %0,{%1,%1};" : "=l"(r) : "f"(v)); return r;
}
__device__ __forceinline__ u64 pk2(float lo, float hi) {
    u64 r; asm("mov.b64 %0,{%1,%2};" : "=l"(r) : "f"(lo), "f"(hi)); return r;
}
__device__ __forceinline__ void unpk2(u64 v, float& lo, float& hi) {
    asm("mov.b64 {%0,%1},%2;" : "=f"(lo), "=f"(hi) : "l"(v));
}
__device__ __forceinline__ u64 f2fma(u64 a, u64 b, u64 c) {
    u64 d; asm("fma.rn.f32x2 %0,%1,%2,%3;" : "=l"(d) : "l"(a), "l"(b), "l"(c)); return d;
}
__device__ __forceinline__ u64 f2add(u64 a, u64 b) {
    u64 d; asm("add.rn.f32x2 %0,%1,%2;" : "=l"(d) : "l"(a), "l"(b)); return d;
}
__device__ __forceinline__ float hsum2(u64 v) {
    float lo, hi; unpk2(v, lo, hi); return lo + hi;
}

// softplus(x) = max(x,0) + log1p(exp(-|x|))
__device__ __forceinline__ float softplus1(float x) {
    float e = __expf(-fabsf(x));
    return fmaxf(x, 0.f) + 0.69314718055994531f * __log2f(1.f + e);
}
// tanh(x) = 1 - 2/(exp(2x)+1)
__device__ __forceinline__ float tanh1(float x) {
    float e = __expf(2.f * x);
    return 1.f - __fdividef(2.f, e + 1.f);
}

// ---------------- main persistent scan kernel --------------------------------
__global__ void __launch_bounds__(NTHR, 1)
sde_scan_kernel(const float* __restrict__ init_noise, const float* __restrict__ dw_noise,
                const float* __restrict__ ts,   const float* __restrict__ embW,
                const float* __restrict__ embb, const float* __restrict__ fW1,
                const float* __restrict__ fb1,  const float* __restrict__ fW2,
                const float* __restrict__ fb2,  const float* __restrict__ fW3,
                const float* __restrict__ fb3,  const float* __restrict__ gW1,
                const float* __restrict__ gb1,  const float* __restrict__ gW2,
                const float* __restrict__ gb2,  const float* __restrict__ gW3,
                const float* __restrict__ gb3)
{
    extern __shared__ __align__(16) char smraw[];
    Smem& sm = *reinterpret_cast<Smem*>(smraw);
    const int tid = threadIdx.x;
    const int wg = tid & 127;            // layer neuron
    const int team = tid >> 7;           // 0,1
    const int r0 = 4 * team;             // team's rows r0..r0+3 (pairs 2t,2t+1)
    const int rowbase = blockIdx.x * RROWS;

    // ---- stage SMEM-resident weights (team-split) ----
    {
        const int j = wg;
        if (team == 0) {
#pragma unroll 4
            for (int k = 0; k < Ln; k++) sm.fW1t[j][k] = fW1[(k + 1) * Hn + j];
#pragma unroll 4
            for (int k = 0; k < Hn; k++) sm.fW2t[j][k] = fW2[k * Hn + j];
        } else {
#pragma unroll 4
            for (int k = 0; k < Ln; k++) sm.gW1t[j][k] = gW1[(k + 1) * Hn + j];
#pragma unroll 4
            for (int k = 0; k < Hn; k++) sm.gW2t[j][k] = gW2[k * Hn + j];
        }
    }

    // ---- per-thread register params ----
    const float w10f = __ldg(fW1 + wg), w10g = __ldg(gW1 + wg);
    const float bf1 = __ldg(fb1 + wg), bf2 = __ldg(fb2 + wg);
    const float bg1 = __ldg(gb1 + wg), bg2 = __ldg(gb2 + wg);
    const int l3 = tid & 63, q3 = tid >> 6;            // f3 mapping (4 pairs x 64 l)
    const float bf3v = __ldg(fb3 + l3);
    const float2 bg3v = *(const float2*)(gb3 + 2 * tid);  // outputs 2tid, 2tid+1

    // ---- z0 = init_noise @ emb_W + emb_b; store z2, zs, zbuf[t=0] ----
    {
        int l = tid & 63, p = tid >> 6;
        float ax = __ldg(embb + l), ay = ax;
#pragma unroll 4
        for (int i = 0; i < DIn; i++) {
            float w = embW[i * Ln + l];
            ax = fmaf(init_noise[(rowbase + 2 * p) * DIn + i], w, ax);
            ay = fmaf(init_noise[(rowbase + 2 * p + 1) * DIn + i], w, ay);
        }
        sm.z2[p][l] = make_float2(ax, ay);
        sm.zs[2 * p][l] = ax;
        sm.zs[2 * p + 1][l] = ay;
        zbuf[(size_t)blockIdx.x * (PAIRS * Ln) + tid] = *(const u64*)&sm.z2[p][l];
    }
    __syncthreads();

    // ---- 511 Euler-Maruyama steps, 4 barriers each --------------------------
    for (int s = 0; s < Tn - 1; s++) {
        const float tcur = __ldg(ts + s);
        const float dt = __ldg(ts + s + 1) - tcur;
        const float sq = sqrtf(dt);
        if (tid < 32) {   // Brownian increments (consumed in ph3, >=2 bars later)
            int p = tid >> 3, n = tid & 7;
            const float* dwp = dw_noise + ((size_t)s * Bn + rowbase + 2 * p) * Nn + n;
            sm.dws[p][n] = make_float2(dwp[0] * sq, dwp[Nn] * sq);
        }

        // ===== ph1: f+g layer1, k-packed lanes (NO weight dup MOVs) =====
        {
            const u64 z0 = dup2f(0.f);
            u64 af0 = z0, af1 = z0, af2 = z0, af3 = z0;
            u64 ag0 = z0, ag1 = z0, ag2 = z0, ag3 = z0;
#pragma unroll 4
            for (int c = 0; c < Ln / 4; c++) {
                ulonglong2 wf = *(const ulonglong2*)&sm.fW1t[wg][4 * c];
                ulonglong2 wgv = *(const ulonglong2*)&sm.gW1t[wg][4 * c];
                ulonglong2 a0 = *(const ulonglong2*)&sm.zs[r0][4 * c];
                ulonglong2 a1 = *(const ulonglong2*)&sm.zs[r0 + 1][4 * c];
                ulonglong2 a2 = *(const ulonglong2*)&sm.zs[r0 + 2][4 * c];
                ulonglong2 a3 = *(const ulonglong2*)&sm.zs[r0 + 3][4 * c];
                af0 = f2fma(wf.x, a0.x, af0);  af0 = f2fma(wf.y, a0.y, af0);
                af1 = f2fma(wf.x, a1.x, af1);  af1 = f2fma(wf.y, a1.y, af1);
                af2 = f2fma(wf.x, a2.x, af2);  af2 = f2fma(wf.y, a2.y, af2);
                af3 = f2fma(wf.x, a3.x, af3);  af3 = f2fma(wf.y, a3.y, af3);
                ag0 = f2fma(wgv.x, a0.x, ag0); ag0 = f2fma(wgv.y, a0.y, ag0);
                ag1 = f2fma(wgv.x, a1.x, ag1); ag1 = f2fma(wgv.y, a1.y, ag1);
                ag2 = f2fma(wgv.x, a2.x, ag2); ag2 = f2fma(wgv.y, a2.y, ag2);
                ag3 = f2fma(wgv.x, a3.x, ag3); ag3 = f2fma(wgv.y, a3.y, ag3);
            }
            const float sf = fmaf(w10f, tcur, bf1);
            const float sg = fmaf(w10g, tcur, bg1);
            sm.h1fs[r0][wg]     = softplus1(sf + hsum2(af0));
            sm.h1fs[r0 + 1][wg] = softplus1(sf + hsum2(af1));
            sm.h1fs[r0 + 2][wg] = softplus1(sf + hsum2(af2));
            sm.h1fs[r0 + 3][wg] = softplus1(sf + hsum2(af3));
            sm.h1gs[r0][wg]     = softplus1(sg + hsum2(ag0));
            sm.h1gs[r0 + 1][wg] = softplus1(sg + hsum2(ag1));
            sm.h1gs[r0 + 2][wg] = softplus1(sg + hsum2(ag2));
            sm.h1gs[r0 + 3][wg] = softplus1(sg + hsum2(ag3));
        }
        __syncthreads();

        // ===== ph2: f+g layer2, k-packed lanes =====
        {
            const u64 z0 = dup2f(0.f);
            u64 af0 = z0, af1 = z0, af2 = z0, af3 = z0;
            u64 ag0 = z0, ag1 = z0, ag2 = z0, ag3 = z0;
#pragma unroll 4
            for (int c = 0; c < Hn / 4; c++) {
                ulonglong2 wf = *(const ulonglong2*)&sm.fW2t[wg][4 * c];
                ulonglong2 wgv = *(const ulonglong2*)&sm.gW2t[wg][4 * c];
                ulonglong2 xf0 = *(const ulonglong2*)&sm.h1fs[r0][4 * c];
                ulonglong2 xf1 = *(const ulonglong2*)&sm.h1fs[r0 + 1][4 * c];
                ulonglong2 xf2 = *(const ulonglong2*)&sm.h1fs[r0 + 2][4 * c];
                ulonglong2 xf3 = *(const ulonglong2*)&sm.h1fs[r0 + 3][4 * c];
                af0 = f2fma(wf.x, xf0.x, af0);  af0 = f2fma(wf.y, xf0.y, af0);
                af1 = f2fma(wf.x, xf1.x, af1);  af1 = f2fma(wf.y, xf1.y, af1);
                af2 = f2fma(wf.x, xf2.x, af2);  af2 = f2fma(wf.y, xf2.y, af2);
                af3 = f2fma(wf.x, xf3.x, af3);  af3 = f2fma(wf.y, xf3.y, af3);
                ulonglong2 xg0 = *(const ulonglong2*)&sm.h1gs[r0][4 * c];
                ulonglong2 xg1 = *(const ulonglong2*)&sm.h1gs[r0 + 1][4 * c];
                ulonglong2 xg2 = *(const ulonglong2*)&sm.h1gs[r0 + 2][4 * c];
                ulonglong2 xg3 = *(const ulonglong2*)&sm.h1gs[r0 + 3][4 * c];
                ag0 = f2fma(wgv.x, xg0.x, ag0); ag0 = f2fma(wgv.y, xg0.y, ag0);
                ag1 = f2fma(wgv.x, xg1.x, ag1); ag1 = f2fma(wgv.y, xg1.y, ag1);
                ag2 = f2fma(wgv.x, xg2.x, ag2); ag2 = f2fma(wgv.y, xg2.y, ag2);
                ag3 = f2fma(wgv.x, xg3.x, ag3); ag3 = f2fma(wgv.y, xg3.y, ag3);
            }
            // rows (r0,r0+1) -> pair 2team; (r0+2,r0+3) -> pair 2team+1
            sm.h2f[2 * team][wg] = make_float2(
                softplus1(bf2 + hsum2(af0)), softplus1(bf2 + hsum2(af1)));
            sm.h2f[2 * team + 1][wg] = make_float2(
                softplus1(bf2 + hsum2(af2)), softplus1(bf2 + hsum2(af3)));
            sm.h2g[2 * team][wg] = make_float2(
                softplus1(bg2 + hsum2(ag0)), softplus1(bg2 + hsum2(ag1)));
            sm.h2g[2 * team + 1][wg] = make_float2(
                softplus1(bg2 + hsum2(ag2)), softplus1(bg2 + hsum2(ag3)));
        }
        __syncthreads();

        // ===== ph3: f3 (thread=(l3,q3)) fused with g3 (R8/R11 schedule) =====
        {
            const u64 one2 = dup2f(1.f);
            u64 a0 = dup2f(bf3v), a1 = dup2f(0.f);
            const float* fp = fW3 + l3;
            u64 acc[PAIRS][2];
#pragma unroll
            for (int p = 0; p < PAIRS; p++) {
                acc[p][0] = dup2f(bg3v.x);
                acc[p][1] = dup2f(bg3v.y);
            }
            const float2* g2 = reinterpret_cast<const float2*>(gW3) + tid;
#pragma unroll 4
            for (int c = 0; c < Hn / 2; c++) {
                u64 w0 = dup2f(__ldg(fp + (2 * c) * Ln));
                u64 w1 = dup2f(__ldg(fp + (2 * c + 1) * Ln));
                a0 = f2fma(w0, *(const u64*)&sm.h2f[q3][2 * c], a0);
                a1 = f2fma(w1, *(const u64*)&sm.h2f[q3][2 * c + 1], a1);
                float2 va = __ldg(g2 + (size_t)(2 * c) * (Ln * Nn / 2));
                float2 vb = __ldg(g2 + (size_t)(2 * c + 1) * (Ln * Nn / 2));
                u64 wa0 = dup2f(va.x), wa1 = dup2f(va.y);
                u64 wb0 = dup2f(vb.x), wb1 = dup2f(vb.y);
#pragma unroll
                for (int p = 0; p < PAIRS; p++) {
                    ulonglong2 h = *(const ulonglong2*)&sm.h2g[p][2 * c];
                    acc[p][0] = f2fma(wa0, h.x, acc[p][0]);
                    acc[p][1] = f2fma(wa1, h.x, acc[p][1]);
                    acc[p][0] = f2fma(wb0, h.y, acc[p][0]);
                    acc[p][1] = f2fma(wb1, h.y, acc[p][1]);
                }
            }
            // f3 output
            {
                u64 t = f2add(a0, a1);
                float lo, hi; unpk2(t, lo, hi);
                sm.fo[q3][l3] = make_float2(tanh1(lo), tanh1(hi));
            }
            // einsum: l = tid>>2, n's = (tid&3)*2, +1; reduce 4 lanes via shfl
            const int l = tid >> 2, nb = (tid & 3) * 2;
#pragma unroll
            for (int p = 0; p < PAIRS; p++) {
                float x0, x1, y0, y1;
                unpk2(acc[p][0], x0, x1);
                unpk2(acc[p][1], y0, y1);
                u64 t0 = pk2(tanh1(x0), tanh1(x1));
                u64 t1 = pk2(tanh1(y0), tanh1(y1));
                u64 pa = f2fma(t0, *(const u64*)&sm.dws[p][nb], dup2f(0.f));
                pa = f2fma(t1, *(const u64*)&sm.dws[p][nb + 1], pa);
                pa = f2fma(one2, __shfl_xor_sync(0xffffffffu, pa, 1), pa);
                pa = f2fma(one2, __shfl_xor_sync(0xffffffffu, pa, 2), pa);
                if ((tid & 3) == 0) *(u64*)&sm.geo[p][l] = pa;
            }
        }
        __syncthreads();

        // ===== ph4: z update (thread = (p,l)); update z2, zs, zbuf =====
        {
            int l = tid & 63, p = tid >> 6;
            const u64 one2 = dup2f(1.f);
            u64 dt2 = dup2f(dt);
            u64 z = *(const u64*)&sm.z2[p][l];
            z = f2fma(*(const u64*)&sm.fo[p][l], dt2, z);
            z = f2fma(one2, *(const u64*)&sm.geo[p][l], z);
            *(u64*)&sm.z2[p][l] = z;
            float lo, hi; unpk2(z, lo, hi);
            sm.zs[2 * p][l] = lo;
            sm.zs[2 * p + 1][l] = hi;
            zbuf[((size_t)(s + 1) * NCTA + blockIdx.x) * (PAIRS * Ln) + tid] = z;
        }
        __syncthreads();
    }
}

// ---------------- readout kernel: x = relu(z@rW1+b1)@rW2+b2 ------------------
#define RO_TS 32   /* time steps per block */
struct __align__(16) RoSmem {
    float rw1t[Hn][68];     // rW1 transposed [j][l]
    float w2t[DOn][130];    // rW2 transposed [d][k], pad 130
    float2 zt[PAIRS][Ln];   // current z tile (2 KB)
    float h1T[RROWS][132];  // stage-1 output, scalar per row, pad 132
};

__global__ void __launch_bounds__(256, 4)
readout_kernel(const float* __restrict__ rW1, const float* __restrict__ rb1,
               const float* __restrict__ rW2, const float* __restrict__ rb2,
               float* __restrict__ out)
{
    extern __shared__ __align__(16) char smraw[];
    RoSmem& sm = *reinterpret_cast<RoSmem*>(smraw);
    const int tid = threadIdx.x;
    const int cta = blockIdx.x & (NCTA - 1);
    const int slice = blockIdx.x >> 7;
    const int rowbase = cta * RROWS;

    // stage rW1 transposed: [j][l], coalesced LDG over j
    {
        const int jj = tid & 127, half = tid >> 7;
#pragma unroll 4
        for (int l = half * 32; l < half * 32 + 32; l++)
            sm.rw1t[jj][l] = rW1[l * Hn + jj];
    }
    // stage rW2 transposed: [d][k]
    for (int i = tid; i < Hn * DOn; i += 256) {
        int d = i & 15, k = i >> 4;
        sm.w2t[d][k] = rW2[i];
    }
    const float rb1v = __ldg(rb1 + (tid & 127));
    const int jr = tid & 127, p0 = (tid >> 7) * 2;             // stage-1 mapping
    const int row2 = tid >> 5, kh5 = (tid >> 4) & 1, d5 = tid & 15;  // stage-2
    const float rb2v = __ldg(rb2 + d5);
    __syncthreads();

    for (int it = 0; it < RO_TS; it++) {
        const int t = slice * RO_TS + it;
        // load z tile
        ((u64*)&sm.zt[0][0])[tid] =
            zbuf[((size_t)t * NCTA + cta) * (PAIRS * Ln) + tid];
        __syncthreads();
        // stage 1: h = relu(z @ rW1 + b1); thread = (jr, 2 pairs); write h1T
        {
            u64 aA[2], aB[2];
            u64 bi = dup2f(rb1v), z0 = dup2f(0.f);
            aA[0] = bi; aA[1] = bi; aB[0] = z0; aB[1] = z0;
#pragma unroll 4
            for (int c = 0; c < Ln / 4; c++) {
                float4 w = *(const float4*)&sm.rw1t[jr][4 * c];
                u64 w0 = dup2f(w.x), w1 = dup2f(w.y), w2 = dup2f(w.z), w3 = dup2f(w.w);
#pragma unroll
                for (int e = 0; e < 2; e++) {
                    ulonglong2 x0 = *(const ulonglong2*)&sm.zt[p0 + e][4 * c];
                    ulonglong2 x1 = *(const ulonglong2*)&sm.zt[p0 + e][4 * c + 2];
                    aA[e] = f2fma(w0, x0.x, aA[e]);
                    aB[e] = f2fma(w1, x0.y, aB[e]);
                    aA[e] = f2fma(w2, x1.x, aA[e]);
                    aB[e] = f2fma(w3, x1.y, aB[e]);
                }
            }
#pragma unroll
            for (int e = 0; e < 2; e++) {
                u64 tv = f2add(aA[e], aB[e]);
                float lo, hi; unpk2(tv, lo, hi);
                sm.h1T[2 * (p0 + e)][jr]     = fmaxf(lo, 0.f);
                sm.h1T[2 * (p0 + e) + 1][jr] = fmaxf(hi, 0.f);
            }
        }
        __syncthreads();
        // stage 2: x = h @ rW2 + b2; thread = (row2, kh5, d5), f32x2 over k-pairs
        {
            u64 acc = dup2f(0.f);
            const float* hT = &sm.h1T[row2][kh5 * 64];
            const float* wT = &sm.w2t[d5][kh5 * 64];
#pragma unroll 8
            for (int kk = 0; kk < 64; kk += 2)
                acc = f2fma(*(const u64*)&hT[kk], *(const u64*)&wT[kk], acc);
            float lo, hi; unpk2(acc, lo, hi);
            float a = lo + hi;
            a += __shfl_xor_sync(0xffffffffu, a, 16);
            if (kh5 == 0) {
                a += rb2v;
                size_t row = (size_t)rowbase + row2;
                out[(row * Tn + t) * DOn + d5] = a;
                if ((t & 7) == 0)
                    out[XFULL + (row * (Tn / 8) + (t >> 3)) * DOn + d5] = a;
            }
        }
        __syncthreads();
    }
}

extern "C" void kernel_launch(void* const* d_in, const int* in_sizes, int n_in,
                              void* d_out, int out_size) {
    (void)in_sizes; (void)n_in; (void)out_size;
    cudaFuncSetAttribute(sde_scan_kernel, cudaFuncAttributeMaxDynamicSharedMemorySize,
                         (int)sizeof(Smem));
    cudaFuncSetAttribute(readout_kernel, cudaFuncAttributeMaxDynamicSharedMemorySize,
                         (int)sizeof(RoSmem));
    sde_scan_kernel<<<NCTA, NTHR, sizeof(Smem)>>>(
        (const float*)d_in[0],  (const float*)d_in[1],  (const float*)d_in[2],
        (const float*)d_in[3],  (const float*)d_in[4],  (const float*)d_in[5],
        (const float*)d_in[6],  (const float*)d_in[7],  (const float*)d_in[8],
        (const float*)d_in[9],  (const float*)d_in[10], (const float*)d_in[11],
        (const float*)d_in[12], (const float*)d_in[13], (const float*)d_in[14],
        (const float*)d_in[15], (const float*)d_in[16]);
    readout_kernel<<<NCTA * (Tn / RO_TS), 256, sizeof(RoSmem)>>>(
        (const float*)d_in[17], (const float*)d_in[18],
        (const float*)d_in[19], (const float*)d_in[20],
        (float*)d_out);
}